// round 1
// baseline (speedup 1.0000x reference)
#include <cuda_runtime.h>
#include <math.h>

#define NN 50000
#define NE 800000
#define DIM 128
#define NH 8
#define HD 16

// ---- scratch (device globals; no allocation allowed) ----
__device__ float gQ[NN * DIM];
__device__ float gK[NN * DIM];
__device__ float gV[NN * DIM];
__device__ float gScore[NE * NH];   // scores, then exp(scores - max)
__device__ float gSmax[NN * NH];
__device__ float gDen[NN * NH];
__device__ float gAgg[NN * DIM];
__device__ float gHid[NN * DIM];    // post-LN1 hidden
__device__ float gF1[NN * 4 * DIM]; // FFN intermediate
__device__ float gY[NN * DIM];      // pre-LN2 residual sum

// ---------------------------------------------------------------------------
// init: accumulators must be reset every launch (graph replays reuse state)
// ---------------------------------------------------------------------------
__global__ void init_kernel(int N) {
    int i = blockIdx.x * blockDim.x + threadIdx.x;
    if (i < N * DIM) gAgg[i] = 0.f;
    if (i < N * NH) { gSmax[i] = -3.402823466e38f; gDen[i] = 0.f; }
}

// ---------------------------------------------------------------------------
// per-node-type QKV projections: one block (128 thr) per node
// thread (h,f): Q[n,h,f] = sum_d x[n,h,d] * W_Q[t,h,d,f]
// ---------------------------------------------------------------------------
__global__ void qkv_kernel(const float* __restrict__ x,
                           const int* __restrict__ node_type,
                           const float* __restrict__ WQ,
                           const float* __restrict__ WK,
                           const float* __restrict__ WV) {
    int n = blockIdx.x;
    int tid = threadIdx.x;
    __shared__ float xs[DIM];
    xs[tid] = x[n * DIM + tid];
    __syncthreads();
    int t = node_type[n];
    int h = tid >> 4, f = tid & 15;
    const float* xr = xs + h * HD;
    int base = ((t * NH + h) * HD) * HD + f;
    float q = 0.f, k = 0.f, v = 0.f;
#pragma unroll
    for (int d = 0; d < HD; d++) {
        float xv = xr[d];
        q = fmaf(xv, WQ[base + d * HD], q);
        k = fmaf(xv, WK[base + d * HD], k);
        v = fmaf(xv, WV[base + d * HD], v);
    }
    gQ[n * DIM + tid] = q;
    gK[n * DIM + tid] = k;
    gV[n * DIM + tid] = v;
}

// ---------------------------------------------------------------------------
// float atomic max (signed max for >=0, unsigned min for <0)
// ---------------------------------------------------------------------------
__device__ __forceinline__ void atomicMaxF(float* addr, float v) {
    if (v >= 0.f) atomicMax((int*)addr, __float_as_int(v));
    else          atomicMin((unsigned int*)addr, __float_as_uint(v));
}

// ---------------------------------------------------------------------------
// edge scores: 128 threads per edge (2 edges / 256-thr block)
// thread (h,f): kt_f = sum_d K[src,h,d]*W_edge[et,h,d,f]; score = sum_f q_f*kt_f
// ---------------------------------------------------------------------------
__global__ void score_kernel(const int* __restrict__ ei,
                             const int* __restrict__ etype,
                             const float* __restrict__ We,
                             const float* __restrict__ mu, int E) {
    int e = blockIdx.x * 2 + (threadIdx.x >> 7);
    if (e >= E) return;
    int tid  = threadIdx.x & 127;
    int lane = threadIdx.x & 31;
    int h = tid >> 4, f = tid & 15;
    int src = ei[e], dst = ei[E + e];
    int et = etype[e];
    float kd = gK[src * DIM + tid];   // K[src, h, f] held by lane f of group h
    float q  = gQ[dst * DIM + tid];
    int wbase = ((et * NH + h) * HD) * HD + f;
    float kt = 0.f;
#pragma unroll
    for (int d = 0; d < HD; d++) {
        float kv = __shfl_sync(0xffffffffu, kd, (lane & 16) | d, 32);
        kt = fmaf(kv, We[wbase + d * HD], kt);
    }
    float s = q * kt;
#pragma unroll
    for (int o = 8; o; o >>= 1) s += __shfl_xor_sync(0xffffffffu, s, o, 32);
    if (f == 0) {
        s = s * 0.25f * mu[h * 5 + et];   // /sqrt(16) * mu[h, etype]
        gScore[e * NH + h] = s;
        atomicMaxF(&gSmax[dst * NH + h], s);
    }
}

// ---------------------------------------------------------------------------
// exp(scores - max), accumulate denominators
// ---------------------------------------------------------------------------
__global__ void exp_kernel(const int* __restrict__ ei, int E) {
    int i = blockIdx.x * blockDim.x + threadIdx.x;
    if (i >= E * NH) return;
    int e = i >> 3, h = i & 7;
    int dst = ei[E + e];
    float ex = expf(gScore[i] - gSmax[dst * NH + h]);
    gScore[i] = ex;
    atomicAdd(&gDen[dst * NH + h], ex);
}

// ---------------------------------------------------------------------------
// weighted scatter aggregation: agg[dst] += V[src] * w   (128 thr / edge)
// ---------------------------------------------------------------------------
__global__ void agg_kernel(const int* __restrict__ ei, int E) {
    int e = blockIdx.x * 2 + (threadIdx.x >> 7);
    if (e >= E) return;
    int tid = threadIdx.x & 127;
    int h = tid >> 4;
    int src = ei[e], dst = ei[E + e];
    float w = gScore[e * NH + h] / (gDen[dst * NH + h] + 1e-10f);
    atomicAdd(&gAgg[dst * DIM + tid], gV[src * DIM + tid] * w);
}

// ---------------------------------------------------------------------------
// out projection (128x128 matvec) + residual + LayerNorm1 -> gHid
// ---------------------------------------------------------------------------
__global__ void oproj_ln1_kernel(const float* __restrict__ x,
                                 const float* __restrict__ Wo,
                                 const float* __restrict__ bo,
                                 const float* __restrict__ g1,
                                 const float* __restrict__ bb1) {
    int n = blockIdx.x;
    int j = threadIdx.x;
    __shared__ float as[DIM];
    __shared__ float red[4];
    __shared__ float red2[4];
    as[j] = gAgg[n * DIM + j];
    __syncthreads();
    float acc = bo[j];
#pragma unroll 8
    for (int i = 0; i < DIM; i++) acc = fmaf(as[i], Wo[i * DIM + j], acc);
    float y = x[n * DIM + j] + acc;

    float s = y;
#pragma unroll
    for (int o = 16; o; o >>= 1) s += __shfl_xor_sync(0xffffffffu, s, o);
    if ((j & 31) == 0) red[j >> 5] = s;
    __syncthreads();
    float mean = (red[0] + red[1] + red[2] + red[3]) * (1.f / DIM);
    float dv = y - mean;
    float s2 = dv * dv;
#pragma unroll
    for (int o = 16; o; o >>= 1) s2 += __shfl_xor_sync(0xffffffffu, s2, o);
    if ((j & 31) == 0) red2[j >> 5] = s2;
    __syncthreads();
    float var = (red2[0] + red2[1] + red2[2] + red2[3]) * (1.f / DIM);
    gHid[n * DIM + j] = dv * rsqrtf(var + 1e-5f) * g1[j] + bb1[j];
}

// ---------------------------------------------------------------------------
// FFN GEMM 1: gF1[M,512] = gelu(gHid[M,128] @ W1 + b1)
// 128x128 tile, BK=32, 256 threads, 8x8 micro-tile
// ---------------------------------------------------------------------------
__global__ void ffn1_kernel(const float* __restrict__ W1,
                            const float* __restrict__ b1v, int M) {
    __shared__ float As[32][132];
    __shared__ float Bs[32][132];
    int tid = threadIdx.x;
    int tx = tid & 15, ty = tid >> 4;
    int m0 = blockIdx.y * 128;
    int n0 = blockIdx.x * 128;
    float acc[8][8];
#pragma unroll
    for (int i = 0; i < 8; i++)
#pragma unroll
        for (int j = 0; j < 8; j++) acc[i][j] = 0.f;

    for (int k0 = 0; k0 < 128; k0 += 32) {
#pragma unroll
        for (int l = tid; l < 1024; l += 256) {
            int m = l >> 3;
            int kq = (l & 7) << 2;
            int gm = m0 + m; if (gm >= M) gm = M - 1;
            float4 a = *(const float4*)(&gHid[gm * 128 + k0 + kq]);
            As[kq][m] = a.x; As[kq + 1][m] = a.y; As[kq + 2][m] = a.z; As[kq + 3][m] = a.w;
        }
#pragma unroll
        for (int l = tid; l < 1024; l += 256) {
            int k = l >> 5;
            int nq = (l & 31) << 2;
            *(float4*)&Bs[k][nq] = *(const float4*)(&W1[(k0 + k) * 512 + n0 + nq]);
        }
        __syncthreads();
#pragma unroll
        for (int k = 0; k < 32; k++) {
            float a[8], b[8];
            *(float4*)&a[0] = *(const float4*)&As[k][ty * 8];
            *(float4*)&a[4] = *(const float4*)&As[k][ty * 8 + 4];
            *(float4*)&b[0] = *(const float4*)&Bs[k][tx * 8];
            *(float4*)&b[4] = *(const float4*)&Bs[k][tx * 8 + 4];
#pragma unroll
            for (int i = 0; i < 8; i++)
#pragma unroll
                for (int j = 0; j < 8; j++) acc[i][j] = fmaf(a[i], b[j], acc[i][j]);
        }
        __syncthreads();
    }
#pragma unroll
    for (int i = 0; i < 8; i++) {
        int gm = m0 + ty * 8 + i;
        if (gm >= M) continue;
#pragma unroll
        for (int j = 0; j < 8; j++) {
            int gn = n0 + tx * 8 + j;
            float v = acc[i][j] + b1v[gn];
            v = 0.5f * v * (1.f + erff(v * 0.7071067811865476f));  // exact gelu
            gF1[gm * 512 + gn] = v;
        }
    }
}

// ---------------------------------------------------------------------------
// FFN GEMM 2: gY[M,128] = gF1[M,512] @ W2 + b2 + gHid (residual)
// ---------------------------------------------------------------------------
__global__ void ffn2_kernel(const float* __restrict__ W2,
                            const float* __restrict__ b2v, int M) {
    __shared__ float As[32][132];
    __shared__ float Bs[32][132];
    int tid = threadIdx.x;
    int tx = tid & 15, ty = tid >> 4;
    int m0 = blockIdx.y * 128;
    float acc[8][8];
#pragma unroll
    for (int i = 0; i < 8; i++)
#pragma unroll
        for (int j = 0; j < 8; j++) acc[i][j] = 0.f;

    for (int k0 = 0; k0 < 512; k0 += 32) {
#pragma unroll
        for (int l = tid; l < 1024; l += 256) {
            int m = l >> 3;
            int kq = (l & 7) << 2;
            int gm = m0 + m; if (gm >= M) gm = M - 1;
            float4 a = *(const float4*)(&gF1[gm * 512 + k0 + kq]);
            As[kq][m] = a.x; As[kq + 1][m] = a.y; As[kq + 2][m] = a.z; As[kq + 3][m] = a.w;
        }
#pragma unroll
        for (int l = tid; l < 1024; l += 256) {
            int k = l >> 5;
            int nq = (l & 31) << 2;
            *(float4*)&Bs[k][nq] = *(const float4*)(&W2[(k0 + k) * 128 + nq]);
        }
        __syncthreads();
#pragma unroll
        for (int k = 0; k < 32; k++) {
            float a[8], b[8];
            *(float4*)&a[0] = *(const float4*)&As[k][ty * 8];
            *(float4*)&a[4] = *(const float4*)&As[k][ty * 8 + 4];
            *(float4*)&b[0] = *(const float4*)&Bs[k][tx * 8];
            *(float4*)&b[4] = *(const float4*)&Bs[k][tx * 8 + 4];
#pragma unroll
            for (int i = 0; i < 8; i++)
#pragma unroll
                for (int j = 0; j < 8; j++) acc[i][j] = fmaf(a[i], b[j], acc[i][j]);
        }
        __syncthreads();
    }
#pragma unroll
    for (int i = 0; i < 8; i++) {
        int gm = m0 + ty * 8 + i;
        if (gm >= M) continue;
#pragma unroll
        for (int j = 0; j < 8; j++) {
            int gn = tx * 8 + j;
            gY[gm * 128 + gn] = acc[i][j] + b2v[gn] + gHid[gm * 128 + gn];
        }
    }
}

// ---------------------------------------------------------------------------
// LayerNorm2 -> d_out
// ---------------------------------------------------------------------------
__global__ void ln2_kernel(const float* __restrict__ g2,
                           const float* __restrict__ bb2,
                           float* __restrict__ out) {
    int n = blockIdx.x;
    int j = threadIdx.x;
    __shared__ float red[4];
    __shared__ float red2[4];
    float y = gY[n * DIM + j];
    float s = y;
#pragma unroll
    for (int o = 16; o; o >>= 1) s += __shfl_xor_sync(0xffffffffu, s, o);
    if ((j & 31) == 0) red[j >> 5] = s;
    __syncthreads();
    float mean = (red[0] + red[1] + red[2] + red[3]) * (1.f / DIM);
    float dv = y - mean;
    float s2 = dv * dv;
#pragma unroll
    for (int o = 16; o; o >>= 1) s2 += __shfl_xor_sync(0xffffffffu, s2, o);
    if ((j & 31) == 0) red2[j >> 5] = s2;
    __syncthreads();
    float var = (red2[0] + red2[1] + red2[2] + red2[3]) * (1.f / DIM);
    out[n * DIM + j] = dv * rsqrtf(var + 1e-5f) * g2[j] + bb2[j];
}

// ---------------------------------------------------------------------------
extern "C" void kernel_launch(void* const* d_in, const int* in_sizes, int n_in,
                              void* d_out, int out_size) {
    const float* x     = (const float*)d_in[0];
    const int*   ei    = (const int*)d_in[1];
    const int*   etype = (const int*)d_in[2];
    const int*   ntype = (const int*)d_in[3];
    const float* WQ    = (const float*)d_in[4];
    const float* WK    = (const float*)d_in[5];
    const float* WV    = (const float*)d_in[6];
    const float* We    = (const float*)d_in[7];
    const float* mu    = (const float*)d_in[8];
    const float* Wo    = (const float*)d_in[9];
    const float* bo    = (const float*)d_in[10];
    const float* ln1g  = (const float*)d_in[11];
    const float* ln1b  = (const float*)d_in[12];
    const float* W1    = (const float*)d_in[13];
    const float* b1    = (const float*)d_in[14];
    const float* W2    = (const float*)d_in[15];
    const float* b2    = (const float*)d_in[16];
    const float* ln2g  = (const float*)d_in[17];
    const float* ln2b  = (const float*)d_in[18];

    int N = in_sizes[0] / DIM;   // 50000
    int E = in_sizes[1] / 2;     // 800000

    init_kernel<<<(N * DIM + 255) / 256, 256>>>(N);
    qkv_kernel<<<N, 128>>>(x, ntype, WQ, WK, WV);
    score_kernel<<<(E + 1) / 2, 256>>>(ei, etype, We, mu, E);
    exp_kernel<<<(E * NH + 255) / 256, 256>>>(ei, E);
    agg_kernel<<<(E + 1) / 2, 256>>>(ei, E);
    oproj_ln1_kernel<<<N, 128>>>(x, Wo, bo, ln1g, ln1b);
    ffn1_kernel<<<dim3(4, (N + 127) / 128), 256>>>(W1, b1, N);
    ffn2_kernel<<<dim3(1, (N + 127) / 128), 256>>>(W2, b2, N);
    ln2_kernel<<<N, 128>>>(ln2g, ln2b, (float*)d_out);
}

// round 2
// speedup vs baseline: 1.6650x; 1.6650x over previous
#include <cuda_runtime.h>
#include <math.h>

#define NN 50000
#define NE 800000
#define DIM 128
#define NH 8
#define HD 16
#define NET 5

// ---- scratch (device globals; no allocation allowed) ----
__device__ float gQ[NN * DIM];
__device__ float gV[NN * DIM];
__device__ float gKt[NET * NN * DIM];   // K transformed by each edge-type matrix
__device__ float gAgg[NN * DIM];
__device__ float gHid[NN * DIM];
__device__ float gF1[NN * 4 * DIM];
__device__ int   gEid[NE];
__device__ int   gCnt[NN];
__device__ int   gCur[NN];
__device__ int   gRow[NN + 1];
__device__ int   gBlkSum[64];
__device__ int   gBlkOff[64];

// ---------------------------------------------------------------------------
// init: zero CSR counters (graph replays reuse device state)
// ---------------------------------------------------------------------------
__global__ void init_kernel(int N) {
    int i = blockIdx.x * blockDim.x + threadIdx.x;
    if (i < N) { gCnt[i] = 0; gCur[i] = 0; }
}

// ---------------------------------------------------------------------------
// per-node-type QKV + per-edge-type K transform (all 5 types precomputed)
// one block (128 thr) per node; thread = (h, f)
// ---------------------------------------------------------------------------
__global__ void qkv_kt_kernel(const float* __restrict__ x,
                              const int* __restrict__ node_type,
                              const float* __restrict__ WQ,
                              const float* __restrict__ WK,
                              const float* __restrict__ WV,
                              const float* __restrict__ We) {
    int n = blockIdx.x;
    int tid = threadIdx.x;
    __shared__ float xs[DIM];
    __shared__ float ks[DIM];
    xs[tid] = x[n * DIM + tid];
    __syncthreads();
    int t = node_type[n];
    int h = tid >> 4, f = tid & 15;
    const float* xr = xs + h * HD;
    int base = ((t * NH + h) * HD) * HD + f;
    float q = 0.f, k = 0.f, v = 0.f;
#pragma unroll
    for (int d = 0; d < HD; d++) {
        float xv = xr[d];
        q = fmaf(xv, WQ[base + d * HD], q);
        k = fmaf(xv, WK[base + d * HD], k);
        v = fmaf(xv, WV[base + d * HD], v);
    }
    gQ[n * DIM + tid] = q;
    gV[n * DIM + tid] = v;
    ks[tid] = k;
    __syncthreads();
    const float* kr = ks + h * HD;
#pragma unroll
    for (int et = 0; et < NET; et++) {
        const float* w = We + ((et * NH + h) * HD) * HD + f;
        float acc = 0.f;
#pragma unroll
        for (int d = 0; d < HD; d++) acc = fmaf(kr[d], w[d * HD], acc);
        gKt[(et * NN + n) * DIM + tid] = acc;
    }
}

// ---------------------------------------------------------------------------
// CSR build: histogram -> block scans -> fill
// ---------------------------------------------------------------------------
__global__ void hist_kernel(const int* __restrict__ ei, int E) {
    int e = blockIdx.x * blockDim.x + threadIdx.x;
    if (e < E) atomicAdd(&gCnt[ei[E + e]], 1);
}

__global__ void scan_local_kernel(int N) {
    __shared__ int sh[1024];
    int t = threadIdx.x;
    int i = blockIdx.x * 1024 + t;
    int v = (i < N) ? gCnt[i] : 0;
    sh[t] = v;
    __syncthreads();
#pragma unroll
    for (int off = 1; off < 1024; off <<= 1) {
        int add = (t >= off) ? sh[t - off] : 0;
        __syncthreads();
        sh[t] += add;
        __syncthreads();
    }
    if (i < N) gRow[i] = sh[t] - v;           // block-local exclusive
    if (t == 1023) gBlkSum[blockIdx.x] = sh[1023];
}

__global__ void scan_block_kernel(int nblk) {
    __shared__ int sh[64];
    int t = threadIdx.x;
    int v = (t < nblk) ? gBlkSum[t] : 0;
    sh[t] = v;
    __syncthreads();
#pragma unroll
    for (int off = 1; off < 64; off <<= 1) {
        int add = (t >= off) ? sh[t - off] : 0;
        __syncthreads();
        sh[t] += add;
        __syncthreads();
    }
    gBlkOff[t] = sh[t] - v;                   // exclusive block offsets
}

__global__ void scan_add_kernel(int N, int E) {
    int i = blockIdx.x * blockDim.x + threadIdx.x;
    if (i < N) gRow[i] += gBlkOff[i >> 10];
    if (i == 0) gRow[N] = E;
}

__global__ void fill_kernel(const int* __restrict__ ei, int E) {
    int e = blockIdx.x * blockDim.x + threadIdx.x;
    if (e < E) {
        int dst = ei[E + e];
        int p = atomicAdd(&gCur[dst], 1);
        gEid[gRow[dst] + p] = e;
    }
}

// ---------------------------------------------------------------------------
// fused attention: per-dst block (128 thr), online softmax, no atomics
// ---------------------------------------------------------------------------
__global__ void attn_kernel(const int* __restrict__ ei,
                            const int* __restrict__ etype,
                            const float* __restrict__ mu, int E) {
    int n = blockIdx.x;
    int tid = threadIdx.x;
    int h = tid >> 4;
    __shared__ int s_src[128];
    __shared__ int s_et[128];
    float q = gQ[n * DIM + tid];
    float muh[NET];
#pragma unroll
    for (int et = 0; et < NET; et++) muh[et] = mu[h * NET + et] * 0.25f;

    float m = -3.402823466e38f, den = 0.f, acc = 0.f;
    int row0 = gRow[n], row1 = gRow[n + 1];
    for (int cs = row0; cs < row1; cs += 128) {
        int c = min(128, row1 - cs);
        if (tid < c) {
            int e = gEid[cs + tid];
            s_src[tid] = ei[e];
            s_et[tid] = etype[e];
        }
        __syncthreads();
        for (int j = 0; j < c; j++) {
            int src = s_src[j], et = s_et[j];
            float kt = gKt[(et * NN + src) * DIM + tid];
            float v  = gV[src * DIM + tid];
            float s = q * kt;
            s += __shfl_xor_sync(0xffffffffu, s, 1);
            s += __shfl_xor_sync(0xffffffffu, s, 2);
            s += __shfl_xor_sync(0xffffffffu, s, 4);
            s += __shfl_xor_sync(0xffffffffu, s, 8);
            s *= muh[et];
            float newm = fmaxf(m, s);
            float scale = __expf(m - newm);
            float p = __expf(s - newm);
            den = den * scale + p;
            acc = fmaf(acc, scale, p * v);
            m = newm;
        }
        __syncthreads();
    }
    gAgg[n * DIM + tid] = acc / (den + 1e-10f);
}

// ---------------------------------------------------------------------------
// out projection + residual + LayerNorm1 -> gHid
// ---------------------------------------------------------------------------
__global__ void oproj_ln1_kernel(const float* __restrict__ x,
                                 const float* __restrict__ Wo,
                                 const float* __restrict__ bo,
                                 const float* __restrict__ g1,
                                 const float* __restrict__ bb1) {
    int n = blockIdx.x;
    int j = threadIdx.x;
    __shared__ float as[DIM];
    __shared__ float red[4];
    __shared__ float red2[4];
    as[j] = gAgg[n * DIM + j];
    __syncthreads();
    float acc = bo[j];
#pragma unroll 8
    for (int i = 0; i < DIM; i++) acc = fmaf(as[i], Wo[i * DIM + j], acc);
    float y = x[n * DIM + j] + acc;

    float s = y;
#pragma unroll
    for (int o = 16; o; o >>= 1) s += __shfl_xor_sync(0xffffffffu, s, o);
    if ((j & 31) == 0) red[j >> 5] = s;
    __syncthreads();
    float mean = (red[0] + red[1] + red[2] + red[3]) * (1.f / DIM);
    float dv = y - mean;
    float s2 = dv * dv;
#pragma unroll
    for (int o = 16; o; o >>= 1) s2 += __shfl_xor_sync(0xffffffffu, s2, o);
    if ((j & 31) == 0) red2[j >> 5] = s2;
    __syncthreads();
    float var = (red2[0] + red2[1] + red2[2] + red2[3]) * (1.f / DIM);
    gHid[n * DIM + j] = dv * rsqrtf(var + 1e-5f) * g1[j] + bb1[j];
}

// ---------------------------------------------------------------------------
// FFN GEMM 1: gF1[M,512] = gelu(gHid[M,128] @ W1 + b1)
// ---------------------------------------------------------------------------
__global__ void ffn1_kernel(const float* __restrict__ W1,
                            const float* __restrict__ b1v, int M) {
    __shared__ float As[32][132];
    __shared__ float Bs[32][132];
    int tid = threadIdx.x;
    int tx = tid & 15, ty = tid >> 4;
    int m0 = blockIdx.y * 128;
    int n0 = blockIdx.x * 128;
    float acc[8][8];
#pragma unroll
    for (int i = 0; i < 8; i++)
#pragma unroll
        for (int j = 0; j < 8; j++) acc[i][j] = 0.f;

    for (int k0 = 0; k0 < 128; k0 += 32) {
#pragma unroll
        for (int l = tid; l < 1024; l += 256) {
            int m = l >> 3;
            int kq = (l & 7) << 2;
            int gm = m0 + m; if (gm >= M) gm = M - 1;
            float4 a = *(const float4*)(&gHid[gm * 128 + k0 + kq]);
            As[kq][m] = a.x; As[kq + 1][m] = a.y; As[kq + 2][m] = a.z; As[kq + 3][m] = a.w;
        }
#pragma unroll
        for (int l = tid; l < 1024; l += 256) {
            int k = l >> 5;
            int nq = (l & 31) << 2;
            *(float4*)&Bs[k][nq] = *(const float4*)(&W1[(k0 + k) * 512 + n0 + nq]);
        }
        __syncthreads();
#pragma unroll
        for (int k = 0; k < 32; k++) {
            float a[8], b[8];
            *(float4*)&a[0] = *(const float4*)&As[k][ty * 8];
            *(float4*)&a[4] = *(const float4*)&As[k][ty * 8 + 4];
            *(float4*)&b[0] = *(const float4*)&Bs[k][tx * 8];
            *(float4*)&b[4] = *(const float4*)&Bs[k][tx * 8 + 4];
#pragma unroll
            for (int i = 0; i < 8; i++)
#pragma unroll
                for (int j = 0; j < 8; j++) acc[i][j] = fmaf(a[i], b[j], acc[i][j]);
        }
        __syncthreads();
    }
#pragma unroll
    for (int i = 0; i < 8; i++) {
        int gm = m0 + ty * 8 + i;
        if (gm >= M) continue;
#pragma unroll
        for (int j = 0; j < 8; j++) {
            int gn = n0 + tx * 8 + j;
            float v = acc[i][j] + b1v[gn];
            v = 0.5f * v * (1.f + erff(v * 0.7071067811865476f));  // exact gelu
            gF1[gm * 512 + gn] = v;
        }
    }
}

// ---------------------------------------------------------------------------
// FFN GEMM 2 + residual + fused LayerNorm2 -> d_out
// each block owns 128 complete rows (full 128-wide output)
// ---------------------------------------------------------------------------
__global__ void ffn2_ln2_kernel(const float* __restrict__ W2,
                                const float* __restrict__ b2v,
                                const float* __restrict__ g2,
                                const float* __restrict__ bb2,
                                float* __restrict__ out, int M) {
    __shared__ float As[32][132];
    __shared__ float Bs[32][132];
    int tid = threadIdx.x;
    int tx = tid & 15, ty = tid >> 4;
    int m0 = blockIdx.y * 128;
    float acc[8][8];
#pragma unroll
    for (int i = 0; i < 8; i++)
#pragma unroll
        for (int j = 0; j < 8; j++) acc[i][j] = 0.f;

    for (int k0 = 0; k0 < 512; k0 += 32) {
#pragma unroll
        for (int l = tid; l < 1024; l += 256) {
            int m = l >> 3;
            int kq = (l & 7) << 2;
            int gm = m0 + m; if (gm >= M) gm = M - 1;
            float4 a = *(const float4*)(&gF1[gm * 512 + k0 + kq]);
            As[kq][m] = a.x; As[kq + 1][m] = a.y; As[kq + 2][m] = a.z; As[kq + 3][m] = a.w;
        }
#pragma unroll
        for (int l = tid; l < 1024; l += 256) {
            int k = l >> 5;
            int nq = (l & 31) << 2;
            *(float4*)&Bs[k][nq] = *(const float4*)(&W2[(k0 + k) * 128 + nq]);
        }
        __syncthreads();
#pragma unroll
        for (int k = 0; k < 32; k++) {
            float a[8], b[8];
            *(float4*)&a[0] = *(const float4*)&As[k][ty * 8];
            *(float4*)&a[4] = *(const float4*)&As[k][ty * 8 + 4];
            *(float4*)&b[0] = *(const float4*)&Bs[k][tx * 8];
            *(float4*)&b[4] = *(const float4*)&Bs[k][tx * 8 + 4];
#pragma unroll
            for (int i = 0; i < 8; i++)
#pragma unroll
                for (int j = 0; j < 8; j++) acc[i][j] = fmaf(a[i], b[j], acc[i][j]);
        }
        __syncthreads();
    }

    // epilogue: residual + LayerNorm over each complete row (tx group = 16 lanes)
    float b2l[8], g2l[8], bbl[8];
#pragma unroll
    for (int j = 0; j < 8; j++) {
        int gn = tx * 8 + j;
        b2l[j] = b2v[gn]; g2l[j] = g2[gn]; bbl[j] = bb2[gn];
    }
#pragma unroll
    for (int i = 0; i < 8; i++) {
        int gm = m0 + ty * 8 + i;
        int gms = (gm < M) ? gm : (M - 1);   // all threads compute (shuffles!)
        float yv[8];
        float ssum = 0.f;
#pragma unroll
        for (int j = 0; j < 8; j++) {
            yv[j] = acc[i][j] + b2l[j] + gHid[gms * 128 + tx * 8 + j];
            ssum += yv[j];
        }
        ssum += __shfl_xor_sync(0xffffffffu, ssum, 1);
        ssum += __shfl_xor_sync(0xffffffffu, ssum, 2);
        ssum += __shfl_xor_sync(0xffffffffu, ssum, 4);
        ssum += __shfl_xor_sync(0xffffffffu, ssum, 8);
        float mean = ssum * (1.f / DIM);
        float s2 = 0.f;
#pragma unroll
        for (int j = 0; j < 8; j++) {
            float d = yv[j] - mean;
            s2 = fmaf(d, d, s2);
        }
        s2 += __shfl_xor_sync(0xffffffffu, s2, 1);
        s2 += __shfl_xor_sync(0xffffffffu, s2, 2);
        s2 += __shfl_xor_sync(0xffffffffu, s2, 4);
        s2 += __shfl_xor_sync(0xffffffffu, s2, 8);
        float rstd = rsqrtf(s2 * (1.f / DIM) + 1e-5f);
        if (gm < M) {
#pragma unroll
            for (int j = 0; j < 8; j++)
                out[gm * 128 + tx * 8 + j] = (yv[j] - mean) * rstd * g2l[j] + bbl[j];
        }
    }
}

// ---------------------------------------------------------------------------
extern "C" void kernel_launch(void* const* d_in, const int* in_sizes, int n_in,
                              void* d_out, int out_size) {
    const float* x     = (const float*)d_in[0];
    const int*   ei    = (const int*)d_in[1];
    const int*   etype = (const int*)d_in[2];
    const int*   ntype = (const int*)d_in[3];
    const float* WQ    = (const float*)d_in[4];
    const float* WK    = (const float*)d_in[5];
    const float* WV    = (const float*)d_in[6];
    const float* We    = (const float*)d_in[7];
    const float* mu    = (const float*)d_in[8];
    const float* Wo    = (const float*)d_in[9];
    const float* bo    = (const float*)d_in[10];
    const float* ln1g  = (const float*)d_in[11];
    const float* ln1b  = (const float*)d_in[12];
    const float* W1    = (const float*)d_in[13];
    const float* b1    = (const float*)d_in[14];
    const float* W2    = (const float*)d_in[15];
    const float* b2    = (const float*)d_in[16];
    const float* ln2g  = (const float*)d_in[17];
    const float* ln2b  = (const float*)d_in[18];

    int N = in_sizes[0] / DIM;   // 50000
    int E = in_sizes[1] / 2;     // 800000
    int nblk = (N + 1023) / 1024;

    init_kernel<<<(N + 255) / 256, 256>>>(N);
    qkv_kt_kernel<<<N, 128>>>(x, ntype, WQ, WK, WV, We);
    hist_kernel<<<(E + 255) / 256, 256>>>(ei, E);
    scan_local_kernel<<<nblk, 1024>>>(N);
    scan_block_kernel<<<1, 64>>>(nblk);
    scan_add_kernel<<<(N + 255) / 256, 256>>>(N, E);
    fill_kernel<<<(E + 255) / 256, 256>>>(ei, E);
    attn_kernel<<<N, 128>>>(ei, etype, mu, E);
    oproj_ln1_kernel<<<N, 128>>>(x, Wo, bo, ln1g, ln1b);
    ffn1_kernel<<<dim3(4, (N + 127) / 128), 256>>>(W1, b1, N);
    ffn2_ln2_kernel<<<dim3(1, (N + 127) / 128), 256>>>(W2, b2, ln2g, ln2b, (float*)d_out, N);
}